// round 3
// baseline (speedup 1.0000x reference)
#include <cuda_runtime.h>

#define BB 2
#define NN 49104
#define CC 20
#define NPAD 49152
#define MAXDET 300
#define NEGV (-1e9f)
#define NEG_HALF (-5e8f)
#define NTHR 1024
#define ELEMS (NPAD / NTHR)   // 48
#define MERGE_M 8192
#define FLATN (CC * MAXDET)   // 6000

// ---------------- device scratch (no allocation allowed) ----------------
__device__ float4 g_boxes[BB * NN];
__device__ float  g_nms_sc[BB * CC * MAXDET];
__device__ int    g_nms_idx[BB * CC * MAXDET];

// ---------------- decode + clip ----------------
__global__ void decode_kernel(const float* __restrict__ anchors,
                              const float* __restrict__ deltas) {
    int i = blockIdx.x * blockDim.x + threadIdx.x;
    if (i >= BB * NN) return;
    float4 a = ((const float4*)anchors)[i];
    float4 d = ((const float4*)deltas)[i];
    float w = __fsub_rn(a.z, a.x);
    float h = __fsub_rn(a.w, a.y);
    float x1 = __fadd_rn(a.x, __fmul_rn(__fmul_rn(d.x, 0.2f), w));
    float y1 = __fadd_rn(a.y, __fmul_rn(__fmul_rn(d.y, 0.2f), h));
    float x2 = __fadd_rn(a.z, __fmul_rn(__fmul_rn(d.z, 0.2f), w));
    float y2 = __fadd_rn(a.w, __fmul_rn(__fmul_rn(d.w, 0.2f), h));
    x1 = fminf(fmaxf(x1, 0.0f), 511.0f);
    y1 = fminf(fmaxf(y1, 0.0f), 511.0f);
    x2 = fminf(fmaxf(x2, 0.0f), 511.0f);
    y2 = fminf(fmaxf(y2, 0.0f), 511.0f);
    g_boxes[i] = make_float4(x1, y1, x2, y2);
}

// ---------------- per (batch, class) greedy NMS ----------------
__global__ __launch_bounds__(NTHR, 1) void nms_kernel(const float* __restrict__ cls) {
    extern __shared__ float s_sc[];          // NPAD scores
    __shared__ float red_v[32];
    __shared__ int   red_i[32];
    __shared__ float s_bv;
    __shared__ int   s_bi;
    __shared__ float4 s_bb;

    int pair = blockIdx.x;
    int b = pair / CC;
    int c = pair % CC;
    int t = threadIdx.x;
    const float4* __restrict__ bx = g_boxes + b * NN;

    // pre-init outputs for this pair (invalid slots stay NEG)
    if (t < MAXDET) {
        g_nms_sc[pair * MAXDET + t] = NEGV;
        g_nms_idx[pair * MAXDET + t] = 0;
    }

    // load + threshold scores, track per-thread max
    float lmax = NEGV;
    int   lidx = 0;
    const float* __restrict__ clsrow = cls + (size_t)b * NN * CC + c;
#pragma unroll 4
    for (int k = 0; k < ELEMS; k++) {
        int n = t + k * NTHR;
        float s = NEGV;
        if (n < NN) {
            float v = __ldg(clsrow + (size_t)n * CC);
            if (v > 0.05f) s = v;
        }
        s_sc[n] = s;
        if (s > lmax) { lmax = s; lidx = n; }
    }

    for (int it = 0; it < MAXDET; it++) {
        // warp-level argmax (tie -> lowest index)
        float v = lmax; int ix = lidx;
#pragma unroll
        for (int off = 16; off > 0; off >>= 1) {
            float ov = __shfl_down_sync(0xffffffffu, v, off);
            int   oi = __shfl_down_sync(0xffffffffu, ix, off);
            if (ov > v || (ov == v && oi < ix)) { v = ov; ix = oi; }
        }
        if ((t & 31) == 0) { red_v[t >> 5] = v; red_i[t >> 5] = ix; }
        __syncthreads();
        if (t < 32) {
            v = red_v[t]; ix = red_i[t];
#pragma unroll
            for (int off = 16; off > 0; off >>= 1) {
                float ov = __shfl_down_sync(0xffffffffu, v, off);
                int   oi = __shfl_down_sync(0xffffffffu, ix, off);
                if (ov > v || (ov == v && oi < ix)) { v = ov; ix = oi; }
            }
            if (t == 0) {
                s_bv = v;
                s_bi = ix;
                if (v > NEG_HALF) {
                    g_nms_sc[pair * MAXDET + it] = v;
                    g_nms_idx[pair * MAXDET + it] = ix;
                    s_bb = bx[ix];
                    s_sc[ix] = NEGV;     // explicit self-suppression (matches .at[i].set)
                }
            }
        }
        __syncthreads();
        if (s_bv <= NEG_HALF) break;     // uniform across block

        float4 bb = s_bb;
        float ab = __fmul_rn(__fsub_rn(bb.z, bb.x), __fsub_rn(bb.w, bb.y));
        lmax = NEGV; lidx = 0;
#pragma unroll 4
        for (int k = 0; k < ELEMS; k++) {
            int n = t + k * NTHR;
            float s = s_sc[n];
            if (s > NEG_HALF) {
                float4 o = __ldg(&bx[n]);
                float xx1 = fmaxf(bb.x, o.x);
                float yy1 = fmaxf(bb.y, o.y);
                float xx2 = fminf(bb.z, o.z);
                float yy2 = fminf(bb.w, o.w);
                float iw = fmaxf(__fsub_rn(xx2, xx1), 0.0f);
                float ih = fmaxf(__fsub_rn(yy2, yy1), 0.0f);
                float inter = __fmul_rn(iw, ih);
                float area = __fmul_rn(__fsub_rn(o.z, o.x), __fsub_rn(o.w, o.y));
                float den = __fadd_rn(__fsub_rn(__fadd_rn(ab, area), inter), 1e-8f);
                float iou = __fdiv_rn(inter, den);
                if (iou > 0.5f) { s = NEGV; s_sc[n] = NEGV; }
            }
            if (s > lmax) { lmax = s; lidx = n; }
        }
        // next iteration's first __syncthreads orders s_sc writes before reuse
    }
}

// ---------------- merge: per-batch global top-300 (exact top_k semantics) -------------
__global__ __launch_bounds__(NTHR, 1) void merge_kernel(float* __restrict__ out) {
    extern __shared__ unsigned long long keys[];   // MERGE_M u64 = 64KB
    int b = blockIdx.x;
    int t = threadIdx.x;

    for (int i = t; i < MERGE_M; i += NTHR) {
        unsigned long long key = 0ull;
        if (i < FLATN) {
            float s = g_nms_sc[b * FLATN + i];
            unsigned u = __float_as_uint(s);
            u = (u & 0x80000000u) ? ~u : (u | 0x80000000u);   // monotonic map
            key = ((unsigned long long)u << 16) | (unsigned)(65535 - i);
        }
        keys[i] = key;
    }
    __syncthreads();

    // bitonic sort, descending
    for (int k = 2; k <= MERGE_M; k <<= 1) {
        for (int j = k >> 1; j > 0; j >>= 1) {
            for (int i = t; i < MERGE_M; i += NTHR) {
                int l = i ^ j;
                if (l > i) {
                    unsigned long long a = keys[i];
                    unsigned long long bk = keys[l];
                    bool up = ((i & k) == 0);                 // descending block
                    bool sw = up ? (a < bk) : (a > bk);
                    if (sw) { keys[i] = bk; keys[l] = a; }
                }
            }
            __syncthreads();
        }
    }

    // emit top-300
    if (t < MAXDET) {
        unsigned long long key = keys[t];
        unsigned u = (unsigned)(key >> 16);
        float s = (u & 0x80000000u) ? __uint_as_float(u ^ 0x80000000u)
                                    : __uint_as_float(~u);
        bool valid = s > NEG_HALF;
        float b0 = -1.0f, b1 = -1.0f, b2 = -1.0f, b3 = -1.0f;
        float sc = -1.0f, lab = -1.0f;
        if (valid) {
            int flat = 65535 - (int)(key & 0xFFFFu);
            int c = flat / MAXDET;
            int bi = g_nms_idx[b * FLATN + flat];
            float4 bb = g_boxes[b * NN + bi];
            b0 = bb.x; b1 = bb.y; b2 = bb.z; b3 = bb.w;
            sc = s;
            lab = (float)c;
        }
        // layout: boxes [B,300,4] | scores [B,300] | labels [B,300], all float32
        out[b * (MAXDET * 4) + t * 4 + 0] = b0;
        out[b * (MAXDET * 4) + t * 4 + 1] = b1;
        out[b * (MAXDET * 4) + t * 4 + 2] = b2;
        out[b * (MAXDET * 4) + t * 4 + 3] = b3;
        out[BB * MAXDET * 4 + b * MAXDET + t] = sc;
        out[BB * MAXDET * 4 + BB * MAXDET + b * MAXDET + t] = lab;
    }
}

// ---------------- launch ----------------
extern "C" void kernel_launch(void* const* d_in, const int* in_sizes, int n_in,
                              void* d_out, int out_size) {
    const float* anchors = (const float*)d_in[1];
    const float* deltas  = (const float*)d_in[2];
    const float* cls     = (const float*)d_in[3];
    float* out = (float*)d_out;

    cudaFuncSetAttribute(nms_kernel, cudaFuncAttributeMaxDynamicSharedMemorySize,
                         NPAD * (int)sizeof(float));
    cudaFuncSetAttribute(merge_kernel, cudaFuncAttributeMaxDynamicSharedMemorySize,
                         MERGE_M * (int)sizeof(unsigned long long));

    decode_kernel<<<(BB * NN + 255) / 256, 256>>>(anchors, deltas);
    nms_kernel<<<BB * CC, NTHR, NPAD * (int)sizeof(float)>>>(cls);
    merge_kernel<<<BB, NTHR, MERGE_M * (int)sizeof(unsigned long long)>>>(out);
}

// round 6
// speedup vs baseline: 21.2450x; 21.2450x over previous
#include <cuda_runtime.h>

#define BB 2
#define NN 49104
#define CC 20
#define NPAD 49152
#define MAXDET 300
#define NEGV (-1e9f)
#define NEG_HALF (-5e8f)
#define NTHR 1024
#define ELEMS (NPAD / NTHR)   // 48
#define MERGE_M 8192
#define FLATN (CC * MAXDET)   // 6000
#define TARGETC 2048
#define CAND_CAP 4096
#define SORTN 4096
#define GSZ 256
#define GW (GSZ / 32)         // 8 mask words

// ---------------- device scratch ----------------
__device__ float4 g_boxes[BB * NN];
__device__ float  g_scores_t[BB * CC * NPAD];
__device__ float  g_nms_sc[BB * FLATN];
__device__ int    g_nms_idx[BB * FLATN];

// ---------------- decode + clip (exact) ----------------
__global__ void decode_kernel(const float* __restrict__ anchors,
                              const float* __restrict__ deltas) {
    int i = blockIdx.x * blockDim.x + threadIdx.x;
    if (i >= BB * NN) return;
    float4 a = ((const float4*)anchors)[i];
    float4 d = ((const float4*)deltas)[i];
    float w = __fsub_rn(a.z, a.x);
    float h = __fsub_rn(a.w, a.y);
    float x1 = __fadd_rn(a.x, __fmul_rn(__fmul_rn(d.x, 0.2f), w));
    float y1 = __fadd_rn(a.y, __fmul_rn(__fmul_rn(d.y, 0.2f), h));
    float x2 = __fadd_rn(a.z, __fmul_rn(__fmul_rn(d.z, 0.2f), w));
    float y2 = __fadd_rn(a.w, __fmul_rn(__fmul_rn(d.w, 0.2f), h));
    x1 = fminf(fmaxf(x1, 0.0f), 511.0f);
    y1 = fminf(fmaxf(y1, 0.0f), 511.0f);
    x2 = fminf(fmaxf(x2, 0.0f), 511.0f);
    y2 = fminf(fmaxf(y2, 0.0f), 511.0f);
    g_boxes[i] = make_float4(x1, y1, x2, y2);
}

// ---------------- transpose cls [B,N,C] -> [B,C,NPAD] ----------------
__global__ void transpose_kernel(const float* __restrict__ cls) {
    int idx = blockIdx.x * blockDim.x + threadIdx.x;
    if (idx >= BB * CC * NPAD) return;
    int b = idx / (CC * NPAD);
    int r = idx - b * (CC * NPAD);
    int c = r / NPAD;
    int n = r - c * NPAD;
    float v = -1.0f;
    if (n < NN) v = __ldg(cls + ((size_t)(b * NN + n)) * CC + c);
    g_scores_t[idx] = v;
}

// exact IoU > 0.5 test (bit-identical to reference expression; symmetric)
__device__ __forceinline__ bool iou_gt_half(float4 a, float4 b) {
    float xx1 = fmaxf(a.x, b.x);
    float yy1 = fmaxf(a.y, b.y);
    float xx2 = fminf(a.z, b.z);
    float yy2 = fminf(a.w, b.w);
    float iw = fmaxf(__fsub_rn(xx2, xx1), 0.0f);
    float ih = fmaxf(__fsub_rn(yy2, yy1), 0.0f);
    float inter = __fmul_rn(iw, ih);
    float aa = __fmul_rn(__fsub_rn(a.z, a.x), __fsub_rn(a.w, a.y));
    float ab = __fmul_rn(__fsub_rn(b.z, b.x), __fsub_rn(b.w, b.y));
    float den = __fadd_rn(__fsub_rn(__fadd_rn(aa, ab), inter), 1e-8f);
    return __fdiv_rn(inter, den) > 0.5f;
}

// ---------------- per (batch, class) sorted-order greedy NMS ----------------
__global__ __launch_bounds__(NTHR, 1) void nms_pair_kernel() {
    extern __shared__ unsigned long long cand[];   // SORTN u64 = 32KB dynamic
    __shared__ int      s_hist[256];
    __shared__ int      s_total;
    __shared__ int      s_target;
    __shared__ unsigned s_prefix;
    __shared__ int      s_cnt;
    __shared__ unsigned long long s_bound;
    __shared__ float4   s_acc[MAXDET];
    __shared__ int      s_accN;
    __shared__ float4   s_gbox[GSZ];
    __shared__ unsigned s_mask[GSZ * GW];
    __shared__ unsigned s_dead[GW];

    int pair = blockIdx.x;
    int b = pair / CC;
    int t = threadIdx.x;
    const float* __restrict__ sc = g_scores_t + (size_t)pair * NPAD;
    const float4* __restrict__ bx = g_boxes + b * NN;

    if (t < MAXDET) {
        g_nms_sc[pair * MAXDET + t] = NEGV;
        g_nms_idx[pair * MAXDET + t] = 0;
    }
    if (t == 0) { s_accN = 0; s_bound = ~0ull; }

    for (;;) {
        __syncthreads();
        unsigned long long bound = s_bound;
        if (t == 0) { s_prefix = 0u; s_total = 0; s_target = 0; }
        __syncthreads();

        // ---- exact 4-level radix select on score bits among remaining ----
        unsigned prefix = 0u;
        for (int lvl = 0; lvl < 4; lvl++) {
            int shift = 24 - lvl * 8;
            if (t < 256) s_hist[t] = 0;
            __syncthreads();
            unsigned himask = (lvl == 0) ? 0u : (0xFFFFFFFFu << (shift + 8));
            for (int k = 0; k < ELEMS; k++) {
                int n = t + k * NTHR;
                float v = sc[n];
                if (v > 0.05f) {
                    unsigned u = __float_as_uint(v);
                    if ((u & himask) == (prefix & himask)) {
                        unsigned long long key =
                            ((unsigned long long)u << 32) | (unsigned)(0xFFFFFFFFu - (unsigned)n);
                        if (key < bound)
                            atomicAdd(&s_hist[(u >> shift) & 255], 1);
                    }
                }
            }
            __syncthreads();
            if (t == 0) {
                if (lvl == 0) {
                    int tot = 0;
                    for (int i = 0; i < 256; i++) tot += s_hist[i];
                    s_total = tot;
                    s_target = tot < TARGETC ? tot : TARGETC;
                }
                if (s_total > 0) {
                    int cum = 0, bin = 0;
                    for (int i = 255; i >= 0; i--) {
                        int h = s_hist[i];
                        if (cum + h >= s_target) { bin = i; break; }
                        cum += h;
                    }
                    s_target -= cum;
                    s_prefix |= (unsigned)bin << shift;
                }
            }
            __syncthreads();
            prefix = s_prefix;
            if (s_total == 0) break;
        }
        if (s_total == 0) break;   // pool exhausted -> remaining slots stay NEG
        unsigned s_star = prefix;  // exact crossing score value

        // ---- compact all remaining with score-bits >= s_star ----
        if (t == 0) s_cnt = 0;
        __syncthreads();
        for (int k = 0; k < ELEMS; k++) {
            int n = t + k * NTHR;
            float v = sc[n];
            if (v > 0.05f) {
                unsigned u = __float_as_uint(v);
                if (u >= s_star) {
                    unsigned long long key =
                        ((unsigned long long)u << 32) | (unsigned)(0xFFFFFFFFu - (unsigned)n);
                    if (key < bound) {
                        int pos = atomicAdd(&s_cnt, 1);
                        if (pos < CAND_CAP) cand[pos] = key;
                    }
                }
            }
        }
        __syncthreads();
        int m = s_cnt < CAND_CAP ? s_cnt : CAND_CAP;
        for (int i = m + t; i < SORTN; i += NTHR) cand[i] = 0ull;
        __syncthreads();

        // ---- bitonic sort descending (SORTN) ----
        for (int k2 = 2; k2 <= SORTN; k2 <<= 1) {
            for (int j = k2 >> 1; j > 0; j >>= 1) {
                for (int i = t; i < SORTN; i += NTHR) {
                    int l = i ^ j;
                    if (l > i) {
                        unsigned long long a = cand[i];
                        unsigned long long bb = cand[l];
                        bool up = ((i & k2) == 0);
                        bool sw = up ? (a < bb) : (a > bb);
                        if (sw) { cand[i] = bb; cand[l] = a; }
                    }
                }
                __syncthreads();
            }
        }
        if (t == 0) s_bound = cand[m - 1];   // smallest key processed this round
        __syncthreads();

        // ---- walk sorted candidates in groups of GSZ ----
        for (int g0 = 0; g0 < m && s_accN < MAXDET; g0 += GSZ) {
            int gsz = min(GSZ, m - g0);
            for (int i = t; i < GSZ * GW; i += NTHR) s_mask[i] = 0u;
            if (t < GW) s_dead[t] = 0u;
            if (t < gsz) {
                unsigned long long key = cand[g0 + t];
                unsigned n = 0xFFFFFFFFu - (unsigned)(key & 0xFFFFFFFFull);
                s_gbox[t] = __ldg(&bx[n]);
            }
            __syncthreads();

            int j = t & (GSZ - 1);
            int seg = t >> 8;     // 4 segments of work per candidate
            if (j < gsz) {
                float4 cb = s_gbox[j];
                // vs already-accepted boxes (strided across 4 segments)
                bool dead = false;
                int accN = s_accN;
                for (int i = seg; i < accN; i += 4)
                    if (iou_gt_half(s_acc[i], cb)) { dead = true; break; }
                if (dead) atomicOr(&s_dead[j >> 5], 1u << (j & 31));
                // triangular pairwise within group: bit j in row i (i < j)
                for (int i = seg; i < j; i += 4)
                    if (iou_gt_half(s_gbox[i], cb))
                        atomicOr(&s_mask[i * GW + (j >> 5)], 1u << (j & 31));
            }
            __syncthreads();

            // serial in-order resolution by thread 0
            if (t == 0) {
                int acc = s_accN;
                int nw = (gsz + 31) >> 5;
                for (int w = 0; w < nw && acc < MAXDET; w++) {
                    unsigned cur = s_dead[w];
                    int bmax = min(32, gsz - w * 32);
                    for (int bit = 0; bit < bmax && acc < MAXDET; bit++) {
                        if (!((cur >> bit) & 1u)) {
                            int jj = w * 32 + bit;
                            unsigned long long key = cand[g0 + jj];
                            unsigned n = 0xFFFFFFFFu - (unsigned)(key & 0xFFFFFFFFull);
                            g_nms_sc[pair * MAXDET + acc] = __uint_as_float((unsigned)(key >> 32));
                            g_nms_idx[pair * MAXDET + acc] = (int)n;
                            s_acc[acc] = s_gbox[jj];
                            acc++;
                            const unsigned* mr = &s_mask[jj * GW];
                            cur |= mr[w];
#pragma unroll
                            for (int w2 = 0; w2 < GW; w2++)
                                if (w2 != w) s_dead[w2] |= mr[w2];
                        }
                    }
                }
                s_accN = acc;
            }
            __syncthreads();
        }
        if (s_accN >= MAXDET) break;
        // else: next round with tighter bound (rare)
    }
}

// ---------------- merge: per-batch global top-300 (exact top_k semantics) ----------
__global__ __launch_bounds__(NTHR, 1) void merge_kernel(float* __restrict__ out) {
    extern __shared__ unsigned long long keys[];   // MERGE_M u64 = 64KB
    int b = blockIdx.x;
    int t = threadIdx.x;

    for (int i = t; i < MERGE_M; i += NTHR) {
        unsigned long long key = 0ull;
        if (i < FLATN) {
            float s = g_nms_sc[b * FLATN + i];
            unsigned u = __float_as_uint(s);
            u = (u & 0x80000000u) ? ~u : (u | 0x80000000u);   // monotonic map
            key = ((unsigned long long)u << 16) | (unsigned)(65535 - i);
        }
        keys[i] = key;
    }
    __syncthreads();

    for (int k = 2; k <= MERGE_M; k <<= 1) {
        for (int j = k >> 1; j > 0; j >>= 1) {
            for (int i = t; i < MERGE_M; i += NTHR) {
                int l = i ^ j;
                if (l > i) {
                    unsigned long long a = keys[i];
                    unsigned long long bk = keys[l];
                    bool up = ((i & k) == 0);
                    bool sw = up ? (a < bk) : (a > bk);
                    if (sw) { keys[i] = bk; keys[l] = a; }
                }
            }
            __syncthreads();
        }
    }

    if (t < MAXDET) {
        unsigned long long key = keys[t];
        unsigned u = (unsigned)(key >> 16);
        float s = (u & 0x80000000u) ? __uint_as_float(u ^ 0x80000000u)
                                    : __uint_as_float(~u);
        bool valid = s > NEG_HALF;
        float b0 = -1.0f, b1 = -1.0f, b2 = -1.0f, b3 = -1.0f;
        float scv = -1.0f, lab = -1.0f;
        if (valid) {
            int flat = 65535 - (int)(key & 0xFFFFu);
            int c = flat / MAXDET;
            int bi = g_nms_idx[b * FLATN + flat];
            float4 bb = g_boxes[b * NN + bi];
            b0 = bb.x; b1 = bb.y; b2 = bb.z; b3 = bb.w;
            scv = s;
            lab = (float)c;
        }
        out[b * (MAXDET * 4) + t * 4 + 0] = b0;
        out[b * (MAXDET * 4) + t * 4 + 1] = b1;
        out[b * (MAXDET * 4) + t * 4 + 2] = b2;
        out[b * (MAXDET * 4) + t * 4 + 3] = b3;
        out[BB * MAXDET * 4 + b * MAXDET + t] = scv;
        out[BB * MAXDET * 4 + BB * MAXDET + b * MAXDET + t] = lab;
    }
}

// ---------------- launch ----------------
extern "C" void kernel_launch(void* const* d_in, const int* in_sizes, int n_in,
                              void* d_out, int out_size) {
    const float* anchors = (const float*)d_in[1];
    const float* deltas  = (const float*)d_in[2];
    const float* cls     = (const float*)d_in[3];
    float* out = (float*)d_out;

    // Opt-in so static (~18KB) + dynamic smem can exceed the 48KB default check.
    cudaFuncSetAttribute(nms_pair_kernel, cudaFuncAttributeMaxDynamicSharedMemorySize,
                         64 * 1024);
    cudaFuncSetAttribute(merge_kernel, cudaFuncAttributeMaxDynamicSharedMemorySize,
                         MERGE_M * (int)sizeof(unsigned long long));

    decode_kernel<<<(BB * NN + 255) / 256, 256>>>(anchors, deltas);
    transpose_kernel<<<(BB * CC * NPAD + 255) / 256, 256>>>(cls);
    nms_pair_kernel<<<BB * CC, NTHR, SORTN * (int)sizeof(unsigned long long)>>>();
    merge_kernel<<<BB, NTHR, MERGE_M * (int)sizeof(unsigned long long)>>>(out);
}

// round 7
// speedup vs baseline: 26.1917x; 1.2328x over previous
#include <cuda_runtime.h>

#define BB 2
#define NN 49104
#define CC 20
#define NPAD 49152
#define MAXDET 300
#define NEGV (-1e9f)
#define NEG_HALF (-5e8f)
#define NTHR 1024
#define ELEMS (NPAD / NTHR)   // 48
#define FLATN (CC * MAXDET)   // 6000
#define TARGETC 2048
#define CAND_CAP 4096
#define GSZ 256
#define GW (GSZ / 32)         // 8 mask words
#define TTN 512               // transpose tile (anchors per block)
#define NTILE (NPAD / TTN)    // 96

// ---------------- device scratch ----------------
__device__ float4 g_boxes[BB * NN];
__device__ float  g_scores_t[BB * CC * NPAD];
__device__ float  g_nms_sc[BB * FLATN];
__device__ int    g_nms_idx[BB * FLATN];

// ---------------- warp-aggregated helpers ----------------
__device__ __forceinline__ void hist_add(int* hist, int bin, bool flag) {
    unsigned act = __ballot_sync(0xffffffffu, flag);
    if (flag) {
        unsigned peers = __match_any_sync(act, bin);
        int leader = __ffs(peers) - 1;
        if ((int)(threadIdx.x & 31) == leader) atomicAdd(&hist[bin], __popc(peers));
    }
}

__device__ __forceinline__ int warp_agg_inc(int* ctr, bool flag) {
    unsigned act = __ballot_sync(0xffffffffu, flag);
    if (flag) {
        int lane = threadIdx.x & 31;
        int leader = __ffs(act) - 1;
        int base = 0;
        if (lane == leader) base = atomicAdd(ctr, __popc(act));
        base = __shfl_sync(act, base, leader);
        return base + __popc(act & ((1u << lane) - 1u));
    }
    return -1;
}

// ---------------- decode + clip (exact) ----------------
__global__ void decode_kernel(const float* __restrict__ anchors,
                              const float* __restrict__ deltas) {
    int i = blockIdx.x * blockDim.x + threadIdx.x;
    if (i >= BB * NN) return;
    float4 a = ((const float4*)anchors)[i];
    float4 d = ((const float4*)deltas)[i];
    float w = __fsub_rn(a.z, a.x);
    float h = __fsub_rn(a.w, a.y);
    float x1 = __fadd_rn(a.x, __fmul_rn(__fmul_rn(d.x, 0.2f), w));
    float y1 = __fadd_rn(a.y, __fmul_rn(__fmul_rn(d.y, 0.2f), h));
    float x2 = __fadd_rn(a.z, __fmul_rn(__fmul_rn(d.z, 0.2f), w));
    float y2 = __fadd_rn(a.w, __fmul_rn(__fmul_rn(d.w, 0.2f), h));
    x1 = fminf(fmaxf(x1, 0.0f), 511.0f);
    y1 = fminf(fmaxf(y1, 0.0f), 511.0f);
    x2 = fminf(fmaxf(x2, 0.0f), 511.0f);
    y2 = fminf(fmaxf(y2, 0.0f), 511.0f);
    g_boxes[i] = make_float4(x1, y1, x2, y2);
}

// ---------------- tiled transpose cls [B,N,C] -> [B,C,NPAD] ----------------
__global__ void transpose_kernel(const float* __restrict__ cls) {
    __shared__ float s[TTN * 21];   // pad 20->21 : conflict-free strided reads
    int tile = blockIdx.x;
    int b = tile / NTILE;
    int n0 = (tile % NTILE) * TTN;
    int t = threadIdx.x;            // 256 threads

    for (int e = t; e < TTN * CC; e += 256) {
        int i = e / CC, c = e - i * CC;
        int n = n0 + i;
        float v = -1.0f;
        if (n < NN) v = __ldg(cls + ((size_t)(b * NN + n)) * CC + c);
        s[i * 21 + c] = v;
    }
    __syncthreads();
    for (int e = t; e < TTN * CC; e += 256) {
        int c = e / TTN, i = e - c * TTN;
        g_scores_t[((size_t)(b * CC + c)) * NPAD + n0 + i] = s[i * 21 + c];
    }
}

// exact IoU > 0.5 test (bit-identical to reference expression; symmetric)
__device__ __forceinline__ bool iou_gt_half(float4 a, float4 b) {
    float xx1 = fmaxf(a.x, b.x);
    float yy1 = fmaxf(a.y, b.y);
    float xx2 = fminf(a.z, b.z);
    float yy2 = fminf(a.w, b.w);
    float iw = fmaxf(__fsub_rn(xx2, xx1), 0.0f);
    float ih = fmaxf(__fsub_rn(yy2, yy1), 0.0f);
    float inter = __fmul_rn(iw, ih);
    float aa = __fmul_rn(__fsub_rn(a.z, a.x), __fsub_rn(a.w, a.y));
    float ab = __fmul_rn(__fsub_rn(b.z, b.x), __fsub_rn(b.w, b.y));
    float den = __fadd_rn(__fsub_rn(__fadd_rn(aa, ab), inter), 1e-8f);
    return __fdiv_rn(inter, den) > 0.5f;
}

// ---------------- per (batch, class) sorted-order greedy NMS ----------------
__global__ __launch_bounds__(NTHR, 1) void nms_pair_kernel() {
    extern __shared__ unsigned long long cand[];   // CAND_CAP u64 = 32KB dynamic
    __shared__ int      s_hist[256];
    __shared__ int      s_total;
    __shared__ int      s_target;
    __shared__ unsigned s_prefix;
    __shared__ int      s_cnt;
    __shared__ unsigned long long s_bound;
    __shared__ float4   s_acc[MAXDET];
    __shared__ int      s_accN;
    __shared__ float4   s_gbox[GSZ];
    __shared__ unsigned s_mask[GSZ * GW];
    __shared__ unsigned s_dead[GW];

    int pair = blockIdx.x;
    int b = pair / CC;
    int t = threadIdx.x;
    const float* __restrict__ sc = g_scores_t + (size_t)pair * NPAD;
    const float4* __restrict__ bx = g_boxes + b * NN;

    if (t < MAXDET) {
        g_nms_sc[pair * MAXDET + t] = NEGV;
        g_nms_idx[pair * MAXDET + t] = 0;
    }
    if (t == 0) { s_accN = 0; s_bound = ~0ull; }

    for (;;) {
        __syncthreads();
        unsigned long long bound = s_bound;
        if (t == 0) { s_prefix = 0u; s_total = 0; s_target = 0; }
        __syncthreads();

        // ---- exact 4-level radix select on score bits among remaining ----
        unsigned prefix = 0u;
        for (int lvl = 0; lvl < 4; lvl++) {
            int shift = 24 - lvl * 8;
            if (t < 256) s_hist[t] = 0;
            __syncthreads();
            unsigned himask = (lvl == 0) ? 0u : (0xFFFFFFFFu << (shift + 8));
            for (int k = 0; k < ELEMS; k++) {
                int n = t + k * NTHR;
                float v = sc[n];
                bool f = false;
                int bin = 0;
                if (v > 0.05f) {
                    unsigned u = __float_as_uint(v);
                    if ((u & himask) == (prefix & himask)) {
                        unsigned long long key =
                            ((unsigned long long)u << 32) | (unsigned)(0xFFFFFFFFu - (unsigned)n);
                        if (key < bound) { f = true; bin = (u >> shift) & 255; }
                    }
                }
                hist_add(s_hist, bin, f);
            }
            __syncthreads();
            if (t == 0) {
                if (lvl == 0) {
                    int tot = 0;
                    for (int i = 0; i < 256; i++) tot += s_hist[i];
                    s_total = tot;
                    s_target = tot < TARGETC ? tot : TARGETC;
                }
                if (s_total > 0) {
                    int cum = 0, bin = 0;
                    for (int i = 255; i >= 0; i--) {
                        int h = s_hist[i];
                        if (cum + h >= s_target) { bin = i; break; }
                        cum += h;
                    }
                    s_target -= cum;
                    s_prefix |= (unsigned)bin << shift;
                }
            }
            __syncthreads();
            prefix = s_prefix;
            if (s_total == 0) break;
        }
        if (s_total == 0) break;   // pool exhausted -> remaining slots stay NEG
        unsigned s_star = prefix;  // exact crossing score value

        // ---- compact all remaining with score-bits >= s_star ----
        if (t == 0) s_cnt = 0;
        __syncthreads();
        for (int k = 0; k < ELEMS; k++) {
            int n = t + k * NTHR;
            float v = sc[n];
            bool f = false;
            unsigned long long key = 0;
            if (v > 0.05f) {
                unsigned u = __float_as_uint(v);
                if (u >= s_star) {
                    key = ((unsigned long long)u << 32) | (unsigned)(0xFFFFFFFFu - (unsigned)n);
                    if (key < bound) f = true;
                }
            }
            int pos = warp_agg_inc(&s_cnt, f);
            if (f && pos < CAND_CAP) cand[pos] = key;
        }
        __syncthreads();
        int m = s_cnt < CAND_CAP ? s_cnt : CAND_CAP;
        int sortn = 512;
        while (sortn < m) sortn <<= 1;         // <= CAND_CAP
        for (int i = m + t; i < sortn; i += NTHR) cand[i] = 0ull;
        __syncthreads();

        // ---- bitonic sort descending (sortn) ----
        for (int k2 = 2; k2 <= sortn; k2 <<= 1) {
            for (int j = k2 >> 1; j > 0; j >>= 1) {
                for (int i = t; i < sortn; i += NTHR) {
                    int l = i ^ j;
                    if (l > i) {
                        unsigned long long a = cand[i];
                        unsigned long long bb = cand[l];
                        bool up = ((i & k2) == 0);
                        bool sw = up ? (a < bb) : (a > bb);
                        if (sw) { cand[i] = bb; cand[l] = a; }
                    }
                }
                __syncthreads();
            }
        }
        if (t == 0) s_bound = cand[m - 1];   // smallest key processed this round
        __syncthreads();

        // ---- walk sorted candidates in groups of GSZ ----
        for (int g0 = 0; g0 < m && s_accN < MAXDET; g0 += GSZ) {
            int gsz = min(GSZ, m - g0);
            for (int i = t; i < GSZ * GW; i += NTHR) s_mask[i] = 0u;
            if (t < GW) s_dead[t] = 0u;
            if (t < gsz) {
                unsigned long long key = cand[g0 + t];
                unsigned n = 0xFFFFFFFFu - (unsigned)(key & 0xFFFFFFFFull);
                s_gbox[t] = __ldg(&bx[n]);
            }
            __syncthreads();

            int j = t & (GSZ - 1);
            int seg = t >> 8;     // 4 segments of work per candidate
            if (j < gsz) {
                float4 cb = s_gbox[j];
                bool dead = false;
                int accN = s_accN;
                for (int i = seg; i < accN; i += 4)
                    if (iou_gt_half(s_acc[i], cb)) { dead = true; break; }
                if (dead) atomicOr(&s_dead[j >> 5], 1u << (j & 31));
                for (int i = seg; i < j; i += 4)
                    if (iou_gt_half(s_gbox[i], cb))
                        atomicOr(&s_mask[i * GW + (j >> 5)], 1u << (j & 31));
            }
            __syncthreads();

            // serial in-order resolution by thread 0 (ffs-skipping over live bits)
            if (t == 0) {
                int acc = s_accN;
                int nw = (gsz + 31) >> 5;
                for (int w = 0; w < nw && acc < MAXDET; w++) {
                    unsigned valid = 0xFFFFFFFFu;
                    int rem = gsz - w * 32;
                    if (rem < 32) valid = (1u << rem) - 1u;
                    unsigned alive = ~s_dead[w] & valid;
                    while (alive && acc < MAXDET) {
                        int bit = __ffs(alive) - 1;
                        int jj = w * 32 + bit;
                        unsigned long long key = cand[g0 + jj];
                        unsigned n = 0xFFFFFFFFu - (unsigned)(key & 0xFFFFFFFFull);
                        g_nms_sc[pair * MAXDET + acc] = __uint_as_float((unsigned)(key >> 32));
                        g_nms_idx[pair * MAXDET + acc] = (int)n;
                        s_acc[acc] = s_gbox[jj];
                        acc++;
                        const unsigned* mr = &s_mask[jj * GW];
                        alive &= ~(1u << bit);
                        alive &= ~mr[w];
#pragma unroll
                        for (int w2 = 0; w2 < GW; w2++)
                            if (w2 > w) s_dead[w2] |= mr[w2];
                    }
                }
                s_accN = acc;
            }
            __syncthreads();
        }
        if (s_accN >= MAXDET) break;
        // else: next round with tighter bound (rare)
    }
}

// ------- merge: exact 6-level u64 radix select of top-300, then tiny sort -------
__global__ __launch_bounds__(NTHR, 1) void merge_kernel(float* __restrict__ out) {
    __shared__ int      s_hist[256];
    __shared__ unsigned long long s_prefix;
    __shared__ int      s_target;
    __shared__ int      s_cnt;
    __shared__ unsigned long long ck[512];
    int b = blockIdx.x;
    int t = threadIdx.x;

    // keys in registers (48-bit: mapped-score<<16 | (65535-i)); unique per i
    unsigned long long key[6];
    bool kv[6];
#pragma unroll
    for (int k = 0; k < 6; k++) {
        int i = t + k * NTHR;
        kv[k] = (i < FLATN);
        key[k] = 0ull;
        if (kv[k]) {
            float s = g_nms_sc[b * FLATN + i];
            unsigned u = __float_as_uint(s);
            u = (u & 0x80000000u) ? ~u : (u | 0x80000000u);
            key[k] = ((unsigned long long)u << 16) | (unsigned)(65535 - i);
        }
    }
    if (t == 0) { s_target = MAXDET; s_prefix = 0ull; }
    __syncthreads();

    unsigned long long prefix = 0ull;
    for (int lvl = 0; lvl < 6; lvl++) {
        int shift = 40 - 8 * lvl;
        if (t < 256) s_hist[t] = 0;
        __syncthreads();
        unsigned long long himask = (lvl == 0) ? 0ull : (~0ull << (shift + 8));
#pragma unroll
        for (int k = 0; k < 6; k++) {
            bool f = kv[k] && ((key[k] & himask) == prefix);
            int bin = (int)((key[k] >> shift) & 255);
            hist_add(s_hist, f ? bin : 0, f);
        }
        __syncthreads();
        if (t == 0) {
            int target = s_target, cum = 0, bin = 0;
            for (int i = 255; i >= 0; i--) {
                int h = s_hist[i];
                if (cum + h >= target) { bin = i; break; }
                cum += h;
            }
            s_target = target - cum;
            s_prefix = prefix | ((unsigned long long)bin << shift);
        }
        __syncthreads();
        prefix = s_prefix;
    }
    // prefix == exact 300th-largest key; keys unique -> exactly 300 selected
    if (t == 0) s_cnt = 0;
    __syncthreads();
#pragma unroll
    for (int k = 0; k < 6; k++) {
        bool f = kv[k] && (key[k] >= prefix);
        int pos = warp_agg_inc(&s_cnt, f);
        if (f && pos < 512) ck[pos] = key[k];
    }
    __syncthreads();
    for (int i = s_cnt + t; i < 512; i += NTHR) ck[i] = 0ull;
    __syncthreads();

    // bitonic sort 512 descending
    for (int k2 = 2; k2 <= 512; k2 <<= 1) {
        for (int j = k2 >> 1; j > 0; j >>= 1) {
            if (t < 512) {
                int i = t, l = i ^ j;
                if (l > i) {
                    unsigned long long a = ck[i];
                    unsigned long long bk = ck[l];
                    bool up = ((i & k2) == 0);
                    bool sw = up ? (a < bk) : (a > bk);
                    if (sw) { ck[i] = bk; ck[l] = a; }
                }
            }
            __syncthreads();
        }
    }

    if (t < MAXDET) {
        unsigned long long kk = ck[t];
        unsigned u = (unsigned)(kk >> 16);
        float s = (u & 0x80000000u) ? __uint_as_float(u ^ 0x80000000u)
                                    : __uint_as_float(~u);
        bool valid = s > NEG_HALF;
        float b0 = -1.0f, b1 = -1.0f, b2 = -1.0f, b3 = -1.0f;
        float scv = -1.0f, lab = -1.0f;
        if (valid) {
            int flat = 65535 - (int)(kk & 0xFFFFull);
            int c = flat / MAXDET;
            int bi = g_nms_idx[b * FLATN + flat];
            float4 bb = g_boxes[b * NN + bi];
            b0 = bb.x; b1 = bb.y; b2 = bb.z; b3 = bb.w;
            scv = s;
            lab = (float)c;
        }
        out[b * (MAXDET * 4) + t * 4 + 0] = b0;
        out[b * (MAXDET * 4) + t * 4 + 1] = b1;
        out[b * (MAXDET * 4) + t * 4 + 2] = b2;
        out[b * (MAXDET * 4) + t * 4 + 3] = b3;
        out[BB * MAXDET * 4 + b * MAXDET + t] = scv;
        out[BB * MAXDET * 4 + BB * MAXDET + b * MAXDET + t] = lab;
    }
}

// ---------------- launch ----------------
extern "C" void kernel_launch(void* const* d_in, const int* in_sizes, int n_in,
                              void* d_out, int out_size) {
    const float* anchors = (const float*)d_in[1];
    const float* deltas  = (const float*)d_in[2];
    const float* cls     = (const float*)d_in[3];
    float* out = (float*)d_out;

    cudaFuncSetAttribute(nms_pair_kernel, cudaFuncAttributeMaxDynamicSharedMemorySize,
                         64 * 1024);

    decode_kernel<<<(BB * NN + 255) / 256, 256>>>(anchors, deltas);
    transpose_kernel<<<BB * NTILE, 256>>>(cls);
    nms_pair_kernel<<<BB * CC, NTHR, CAND_CAP * (int)sizeof(unsigned long long)>>>();
    merge_kernel<<<BB, NTHR>>>(out);
}

// round 11
// speedup vs baseline: 26.5233x; 1.0127x over previous
#include <cuda_runtime.h>

#define BB 2
#define NN 49104
#define CC 20
#define NPAD 49152
#define MAXDET 300
#define NEGV (-1e9f)
#define NEG_HALF (-5e8f)
#define NTHR 1024
#define ELEMS (NPAD / NTHR)   // 48
#define FLATN (CC * MAXDET)   // 6000
#define TARGETC 1792
#define CAND_CAP 4096
#define GSZ 256
#define GW (GSZ / 32)         // 8 mask words
#define TTN 512               // transpose tile (anchors per block)
#define NTILE (NPAD / TTN)    // 96
#define HBINS 32768           // 15-bit score histogram (bits 30:16)

// ---------------- device scratch ----------------
__device__ float4 g_boxes[BB * NN];
__device__ float  g_scores_t[BB * CC * NPAD];
__device__ float  g_nms_sc[BB * FLATN];
__device__ int    g_nms_idx[BB * FLATN];

// ---------------- warp-aggregated helpers ----------------
__device__ __forceinline__ void hist_add(int* hist, int bin, bool flag) {
    unsigned act = __ballot_sync(0xffffffffu, flag);
    if (flag) {
        unsigned peers = __match_any_sync(act, bin);
        int leader = __ffs(peers) - 1;
        if ((int)(threadIdx.x & 31) == leader) atomicAdd(&hist[bin], __popc(peers));
    }
}

__device__ __forceinline__ int warp_agg_inc(int* ctr, bool flag) {
    unsigned act = __ballot_sync(0xffffffffu, flag);
    if (flag) {
        int lane = threadIdx.x & 31;
        int leader = __ffs(act) - 1;
        int base = 0;
        if (lane == leader) base = atomicAdd(ctr, __popc(act));
        base = __shfl_sync(act, base, leader);
        return base + __popc(act & ((1u << lane) - 1u));
    }
    return -1;
}

// ---------------- decode + clip (exact) ----------------
__global__ void decode_kernel(const float* __restrict__ anchors,
                              const float* __restrict__ deltas) {
    int i = blockIdx.x * blockDim.x + threadIdx.x;
    if (i >= BB * NN) return;
    float4 a = ((const float4*)anchors)[i];
    float4 d = ((const float4*)deltas)[i];
    float w = __fsub_rn(a.z, a.x);
    float h = __fsub_rn(a.w, a.y);
    float x1 = __fadd_rn(a.x, __fmul_rn(__fmul_rn(d.x, 0.2f), w));
    float y1 = __fadd_rn(a.y, __fmul_rn(__fmul_rn(d.y, 0.2f), h));
    float x2 = __fadd_rn(a.z, __fmul_rn(__fmul_rn(d.z, 0.2f), w));
    float y2 = __fadd_rn(a.w, __fmul_rn(__fmul_rn(d.w, 0.2f), h));
    x1 = fminf(fmaxf(x1, 0.0f), 511.0f);
    y1 = fminf(fmaxf(y1, 0.0f), 511.0f);
    x2 = fminf(fmaxf(x2, 0.0f), 511.0f);
    y2 = fminf(fmaxf(y2, 0.0f), 511.0f);
    g_boxes[i] = make_float4(x1, y1, x2, y2);
}

// ---------------- tiled transpose cls [B,N,C] -> [B,C,NPAD] ----------------
__global__ void transpose_kernel(const float* __restrict__ cls) {
    __shared__ float s[TTN * 21];
    int tile = blockIdx.x;
    int b = tile / NTILE;
    int n0 = (tile % NTILE) * TTN;
    int t = threadIdx.x;            // 256 threads

    for (int e = t; e < TTN * CC; e += 256) {
        int i = e / CC, c = e - i * CC;
        int n = n0 + i;
        float v = -1.0f;
        if (n < NN) v = __ldg(cls + ((size_t)(b * NN + n)) * CC + c);
        s[i * 21 + c] = v;
    }
    __syncthreads();
    for (int e = t; e < TTN * CC; e += 256) {
        int c = e / TTN, i = e - c * TTN;
        g_scores_t[((size_t)(b * CC + c)) * NPAD + n0 + i] = s[i * 21 + c];
    }
}

// exact IoU > 0.5 test (bit-identical to reference expression; symmetric)
__device__ __forceinline__ bool iou_gt_half(float4 a, float4 b) {
    float xx1 = fmaxf(a.x, b.x);
    float yy1 = fmaxf(a.y, b.y);
    float xx2 = fminf(a.z, b.z);
    float yy2 = fminf(a.w, b.w);
    float iw = fmaxf(__fsub_rn(xx2, xx1), 0.0f);
    float ih = fmaxf(__fsub_rn(yy2, yy1), 0.0f);
    float inter = __fmul_rn(iw, ih);
    float aa = __fmul_rn(__fsub_rn(a.z, a.x), __fsub_rn(a.w, a.y));
    float ab = __fmul_rn(__fsub_rn(b.z, b.x), __fsub_rn(b.w, b.y));
    float den = __fadd_rn(__fsub_rn(__fadd_rn(aa, ab), inter), 1e-8f);
    return __fdiv_rn(inter, den) > 0.5f;
}

// ---------------- per (batch, class) sorted-order greedy NMS ----------------
__global__ __launch_bounds__(NTHR, 1) void nms_pair_kernel() {
    extern __shared__ int dyn[];
    int* s_hist = dyn;                                              // HBINS ints
    unsigned long long* cand = (unsigned long long*)(dyn + HBINS);  // CAND_CAP u64
    __shared__ int      s_part[NTHR];
    __shared__ int      s_total;
    __shared__ unsigned s_star_sh;
    __shared__ int      s_cnt;
    __shared__ unsigned long long s_bound;
    __shared__ float4   s_acc[MAXDET];
    __shared__ int      s_accN;
    __shared__ float4   s_gbox[GSZ];
    __shared__ unsigned s_mask[GSZ * GW];
    __shared__ unsigned s_dead[GW];

    int pair = blockIdx.x;
    int b = pair / CC;
    int t = threadIdx.x;
    const float* __restrict__ sc = g_scores_t + (size_t)pair * NPAD;
    const float4* __restrict__ bx = g_boxes + b * NN;

    if (t < MAXDET) {
        g_nms_sc[pair * MAXDET + t] = NEGV;
        g_nms_idx[pair * MAXDET + t] = 0;
    }
    if (t == 0) { s_accN = 0; s_bound = ~0ull; }

    for (;;) {
        __syncthreads();
        unsigned long long bound = s_bound;
        if (t == 0) { s_total = 0; s_star_sh = 0u; }
        // zero histogram (uint4 stores)
        {
            uint4 z = make_uint4(0, 0, 0, 0);
            uint4* h4 = (uint4*)s_hist;
#pragma unroll
            for (int k = 0; k < HBINS / 4 / NTHR; k++)
                h4[t + k * NTHR] = z;
        }
        __syncthreads();

        // ---- single-pass 15-bit histogram over remaining pool ----
        for (int k = 0; k < ELEMS; k++) {
            int n = t + k * NTHR;
            float v = sc[n];
            if (v > 0.05f) {
                unsigned u = __float_as_uint(v);
                unsigned long long key =
                    ((unsigned long long)u << 32) | (unsigned)(0xFFFFFFFFu - (unsigned)n);
                if (key < bound) atomicAdd(&s_hist[u >> 16], 1);
            }
        }
        __syncthreads();

        // per-thread partial sums over 32-bin groups + total
        {
            int base = t * 32, sum = 0;
#pragma unroll
            for (int i = 0; i < 32; i++) sum += s_hist[base + i];
            s_part[t] = sum;
#pragma unroll
            for (int off = 16; off > 0; off >>= 1)
                sum += __shfl_down_sync(0xffffffffu, sum, off);
            if ((t & 31) == 0) atomicAdd(&s_total, sum);
        }
        __syncthreads();
        if (s_total == 0) break;     // pool exhausted -> remaining slots stay NEG

        if (t == 0) {
            int target = s_total < TARGETC ? s_total : TARGETC;
            int cum = 0, g = 0;
            for (int p = NTHR - 1; p >= 0; p--) {
                int h = s_part[p];
                if (cum + h >= target) { g = p; break; }
                cum += h;
            }
            int bin = g * 32;
            for (int i = g * 32 + 31; i >= g * 32; i--) {
                cum += s_hist[i];
                if (cum >= target) { bin = i; break; }
            }
            s_star_sh = (unsigned)bin << 16;
            s_cnt = 0;
        }
        __syncthreads();
        unsigned s_star = s_star_sh;

        // ---- compact all remaining with score-bits >= s_star ----
        for (int k = 0; k < ELEMS; k++) {
            int n = t + k * NTHR;
            float v = sc[n];
            bool f = false;
            unsigned long long key = 0;
            if (v > 0.05f) {
                unsigned u = __float_as_uint(v);
                if (u >= s_star) {
                    key = ((unsigned long long)u << 32) | (unsigned)(0xFFFFFFFFu - (unsigned)n);
                    if (key < bound) f = true;
                }
            }
            int pos = warp_agg_inc(&s_cnt, f);
            if (f && pos < CAND_CAP) cand[pos] = key;
        }
        __syncthreads();
        int m = s_cnt < CAND_CAP ? s_cnt : CAND_CAP;
        int sortn = 512;
        while (sortn < m) sortn <<= 1;         // typically 2048
        for (int i = m + t; i < sortn; i += NTHR) cand[i] = 0ull;
        __syncthreads();

        // ---- bitonic sort descending; warp-local sync when safe ----
        for (int k2 = 2; k2 <= sortn; k2 <<= 1) {
            for (int j = k2 >> 1; j > 0; j >>= 1) {
                for (int i = t; i < sortn; i += NTHR) {
                    int l = i ^ j;
                    if (l > i) {
                        unsigned long long a = cand[i];
                        unsigned long long bb = cand[l];
                        bool up = ((i & k2) == 0);
                        bool sw = up ? (a < bb) : (a > bb);
                        if (sw) { cand[i] = bb; cand[l] = a; }
                    }
                }
                int nj = (j > 1) ? (j >> 1) : k2;   // next exchange distance
                if (j >= 32 || nj >= 32) __syncthreads();
                else __syncwarp();
            }
        }
        __syncthreads();
        if (t == 0) s_bound = cand[m - 1];   // smallest key processed this round
        __syncthreads();

        // ---- walk sorted candidates in groups of GSZ ----
        for (int g0 = 0; g0 < m && s_accN < MAXDET; g0 += GSZ) {
            int gsz = min(GSZ, m - g0);
            for (int i = t; i < GSZ * GW; i += NTHR) s_mask[i] = 0u;
            if (t < GW) s_dead[t] = 0u;
            if (t < gsz) {
                unsigned long long key = cand[g0 + t];
                unsigned n = 0xFFFFFFFFu - (unsigned)(key & 0xFFFFFFFFull);
                s_gbox[t] = __ldg(&bx[n]);
            }
            __syncthreads();

            int j = t & (GSZ - 1);
            int seg = t >> 8;     // 4 segments of work per candidate
            if (j < gsz) {
                float4 cb = s_gbox[j];
                bool dead = false;
                int accN = s_accN;
                for (int i = seg; i < accN; i += 4)
                    if (iou_gt_half(s_acc[i], cb)) { dead = true; break; }
                if (dead) atomicOr(&s_dead[j >> 5], 1u << (j & 31));
                for (int i = seg; i < j; i += 4)
                    if (iou_gt_half(s_gbox[i], cb))
                        atomicOr(&s_mask[i * GW + (j >> 5)], 1u << (j & 31));
            }
            __syncthreads();

            // serial in-order resolution by thread 0 (ffs-skipping over live bits)
            if (t == 0) {
                int acc = s_accN;
                int nw = (gsz + 31) >> 5;
                for (int w = 0; w < nw && acc < MAXDET; w++) {
                    unsigned valid = 0xFFFFFFFFu;
                    int rem = gsz - w * 32;
                    if (rem < 32) valid = (1u << rem) - 1u;
                    unsigned alive = ~s_dead[w] & valid;
                    while (alive && acc < MAXDET) {
                        int bit = __ffs(alive) - 1;
                        int jj = w * 32 + bit;
                        unsigned long long key = cand[g0 + jj];
                        unsigned n = 0xFFFFFFFFu - (unsigned)(key & 0xFFFFFFFFull);
                        g_nms_sc[pair * MAXDET + acc] = __uint_as_float((unsigned)(key >> 32));
                        g_nms_idx[pair * MAXDET + acc] = (int)n;
                        s_acc[acc] = s_gbox[jj];
                        acc++;
                        const unsigned* mr = &s_mask[jj * GW];
                        alive &= ~(1u << bit);
                        alive &= ~mr[w];
#pragma unroll
                        for (int w2 = 0; w2 < GW; w2++)
                            if (w2 > w) s_dead[w2] |= mr[w2];
                    }
                }
                s_accN = acc;
            }
            __syncthreads();
        }
        if (s_accN >= MAXDET) break;
        // else: next round with tighter bound (rare)
    }
}

// ------- merge: exact 6-level u64 radix select of top-300, then tiny sort -------
__global__ __launch_bounds__(NTHR, 1) void merge_kernel(float* __restrict__ out) {
    __shared__ int      s_hist[256];
    __shared__ unsigned long long s_prefix;
    __shared__ int      s_target;
    __shared__ int      s_cnt;
    __shared__ unsigned long long ck[512];
    int b = blockIdx.x;
    int t = threadIdx.x;

    unsigned long long key[6];
    bool kv[6];
#pragma unroll
    for (int k = 0; k < 6; k++) {
        int i = t + k * NTHR;
        kv[k] = (i < FLATN);
        key[k] = 0ull;
        if (kv[k]) {
            float s = g_nms_sc[b * FLATN + i];
            unsigned u = __float_as_uint(s);
            u = (u & 0x80000000u) ? ~u : (u | 0x80000000u);
            key[k] = ((unsigned long long)u << 16) | (unsigned)(65535 - i);
        }
    }
    if (t == 0) { s_target = MAXDET; s_prefix = 0ull; }
    __syncthreads();

    unsigned long long prefix = 0ull;
    for (int lvl = 0; lvl < 6; lvl++) {
        int shift = 40 - 8 * lvl;
        if (t < 256) s_hist[t] = 0;
        __syncthreads();
        unsigned long long himask = (lvl == 0) ? 0ull : (~0ull << (shift + 8));
#pragma unroll
        for (int k = 0; k < 6; k++) {
            bool f = kv[k] && ((key[k] & himask) == prefix);
            int bin = (int)((key[k] >> shift) & 255);
            hist_add(s_hist, f ? bin : 0, f);
        }
        __syncthreads();
        if (t == 0) {
            int target = s_target, cum = 0, bin = 0;
            for (int i = 255; i >= 0; i--) {
                int h = s_hist[i];
                if (cum + h >= target) { bin = i; break; }
                cum += h;
            }
            s_target = target - cum;
            s_prefix = prefix | ((unsigned long long)bin << shift);
        }
        __syncthreads();
        prefix = s_prefix;
    }
    if (t == 0) s_cnt = 0;
    __syncthreads();
#pragma unroll
    for (int k = 0; k < 6; k++) {
        bool f = kv[k] && (key[k] >= prefix);
        int pos = warp_agg_inc(&s_cnt, f);
        if (f && pos < 512) ck[pos] = key[k];
    }
    __syncthreads();
    for (int i = s_cnt + t; i < 512; i += NTHR) ck[i] = 0ull;
    __syncthreads();

    for (int k2 = 2; k2 <= 512; k2 <<= 1) {
        for (int j = k2 >> 1; j > 0; j >>= 1) {
            if (t < 512) {
                int i = t, l = i ^ j;
                if (l > i) {
                    unsigned long long a = ck[i];
                    unsigned long long bk = ck[l];
                    bool up = ((i & k2) == 0);
                    bool sw = up ? (a < bk) : (a > bk);
                    if (sw) { ck[i] = bk; ck[l] = a; }
                }
            }
            __syncthreads();
        }
    }

    if (t < MAXDET) {
        unsigned long long kk = ck[t];
        unsigned u = (unsigned)(kk >> 16);
        float s = (u & 0x80000000u) ? __uint_as_float(u ^ 0x80000000u)
                                    : __uint_as_float(~u);
        bool valid = s > NEG_HALF;
        float b0 = -1.0f, b1 = -1.0f, b2 = -1.0f, b3 = -1.0f;
        float scv = -1.0f, lab = -1.0f;
        if (valid) {
            int flat = 65535 - (int)(kk & 0xFFFFull);
            int c = flat / MAXDET;
            int bi = g_nms_idx[b * FLATN + flat];
            float4 bb = g_boxes[b * NN + bi];
            b0 = bb.x; b1 = bb.y; b2 = bb.z; b3 = bb.w;
            scv = s;
            lab = (float)c;
        }
        out[b * (MAXDET * 4) + t * 4 + 0] = b0;
        out[b * (MAXDET * 4) + t * 4 + 1] = b1;
        out[b * (MAXDET * 4) + t * 4 + 2] = b2;
        out[b * (MAXDET * 4) + t * 4 + 3] = b3;
        out[BB * MAXDET * 4 + b * MAXDET + t] = scv;
        out[BB * MAXDET * 4 + BB * MAXDET + b * MAXDET + t] = lab;
    }
}

// ---------------- launch ----------------
extern "C" void kernel_launch(void* const* d_in, const int* in_sizes, int n_in,
                              void* d_out, int out_size) {
    const float* anchors = (const float*)d_in[1];
    const float* deltas  = (const float*)d_in[2];
    const float* cls     = (const float*)d_in[3];
    float* out = (float*)d_out;

    int dynBytes = HBINS * (int)sizeof(int) + CAND_CAP * (int)sizeof(unsigned long long);
    cudaFuncSetAttribute(nms_pair_kernel, cudaFuncAttributeMaxDynamicSharedMemorySize,
                         dynBytes);

    decode_kernel<<<(BB * NN + 255) / 256, 256>>>(anchors, deltas);
    transpose_kernel<<<BB * NTILE, 256>>>(cls);
    nms_pair_kernel<<<BB * CC, NTHR, dynBytes>>>();
    merge_kernel<<<BB, NTHR>>>(out);
}

// round 13
// speedup vs baseline: 41.4002x; 1.5609x over previous
#include <cuda_runtime.h>

#define BB 2
#define NN 49104
#define CC 20
#define NPAD 49152
#define MAXDET 300
#define NEGV (-1e9f)
#define NEG_HALF (-5e8f)
#define NTHR 1024
#define ELEMS (NPAD / NTHR)   // 48
#define FLATN (CC * MAXDET)   // 6000
#define TARGETC 1792
#define CAND_CAP 4096
#define GSZ 256
#define GW (GSZ / 32)         // 8 mask words
#define TTN 512
#define NTILE (NPAD / TTN)    // 96
#define TAU 0.589f            // round-0 pool cutoff (E[m] ~ 900); any tau>=0.05 is exact

// ---------------- device scratch ----------------
__device__ float4 g_boxes[BB * NN];
__device__ float  g_scores_t[BB * CC * NPAD];
__device__ float  g_nms_sc[BB * FLATN];
__device__ int    g_nms_idx[BB * FLATN];

// ---------------- warp helpers ----------------
__device__ __forceinline__ void hist_add(int* hist, int bin, bool flag) {
    unsigned act = __ballot_sync(0xffffffffu, flag);
    if (flag) {
        unsigned peers = __match_any_sync(act, bin);
        int leader = __ffs(peers) - 1;
        if ((int)(threadIdx.x & 31) == leader) atomicAdd(&hist[bin], __popc(peers));
    }
}

__device__ __forceinline__ int warp_agg_inc(int* ctr, bool flag) {
    unsigned act = __ballot_sync(0xffffffffu, flag);
    if (flag) {
        int lane = threadIdx.x & 31;
        int leader = __ffs(act) - 1;
        int base = 0;
        if (lane == leader) base = atomicAdd(ctr, __popc(act));
        base = __shfl_sync(act, base, leader);
        return base + __popc(act & ((1u << lane) - 1u));
    }
    return -1;
}

// ---------------- fused decode + transpose ----------------
__global__ void prep_kernel(const float* __restrict__ anchors,
                            const float* __restrict__ deltas,
                            const float* __restrict__ cls) {
    __shared__ float s[TTN * 21];
    int blk = blockIdx.x;
    int t = threadIdx.x;
    if (blk < 384) {                       // decode+clip (exact)
        int i = blk * 256 + t;
        if (i >= BB * NN) return;
        float4 a = ((const float4*)anchors)[i];
        float4 d = ((const float4*)deltas)[i];
        float w = __fsub_rn(a.z, a.x);
        float h = __fsub_rn(a.w, a.y);
        float x1 = __fadd_rn(a.x, __fmul_rn(__fmul_rn(d.x, 0.2f), w));
        float y1 = __fadd_rn(a.y, __fmul_rn(__fmul_rn(d.y, 0.2f), h));
        float x2 = __fadd_rn(a.z, __fmul_rn(__fmul_rn(d.z, 0.2f), w));
        float y2 = __fadd_rn(a.w, __fmul_rn(__fmul_rn(d.w, 0.2f), h));
        x1 = fminf(fmaxf(x1, 0.0f), 511.0f);
        y1 = fminf(fmaxf(y1, 0.0f), 511.0f);
        x2 = fminf(fmaxf(x2, 0.0f), 511.0f);
        y2 = fminf(fmaxf(y2, 0.0f), 511.0f);
        g_boxes[i] = make_float4(x1, y1, x2, y2);
    } else {                               // tiled transpose
        int tile = blk - 384;
        int b = tile / NTILE;
        int n0 = (tile % NTILE) * TTN;
        for (int e = t; e < TTN * CC; e += 256) {
            int i = e / CC, c = e - i * CC;
            int n = n0 + i;
            float v = -1.0f;
            if (n < NN) v = __ldg(cls + ((size_t)(b * NN + n)) * CC + c);
            s[i * 21 + c] = v;
        }
        __syncthreads();
        for (int e = t; e < TTN * CC; e += 256) {
            int c = e / TTN, i = e - c * TTN;
            g_scores_t[((size_t)(b * CC + c)) * NPAD + n0 + i] = s[i * 21 + c];
        }
    }
}

// exact IoU > 0.5 (bit-identical to reference; symmetric)
__device__ __forceinline__ bool iou_gt_half(float4 a, float4 b) {
    float xx1 = fmaxf(a.x, b.x);
    float yy1 = fmaxf(a.y, b.y);
    float xx2 = fminf(a.z, b.z);
    float yy2 = fminf(a.w, b.w);
    float iw = fmaxf(__fsub_rn(xx2, xx1), 0.0f);
    float ih = fmaxf(__fsub_rn(yy2, yy1), 0.0f);
    float inter = __fmul_rn(iw, ih);
    float aa = __fmul_rn(__fsub_rn(a.z, a.x), __fsub_rn(a.w, a.y));
    float ab = __fmul_rn(__fsub_rn(b.z, b.x), __fsub_rn(b.w, b.y));
    float den = __fadd_rn(__fsub_rn(__fadd_rn(aa, ab), inter), 1e-8f);
    return __fdiv_rn(inter, den) > 0.5f;
}

// ---------------- per (batch, class) sorted-order greedy NMS ----------------
__global__ __launch_bounds__(NTHR, 1) void nms_pair_kernel() {
    extern __shared__ unsigned long long cand[];   // CAND_CAP u64 = 32KB dynamic
    __shared__ int      s_hist[256];
    __shared__ int      s_total;
    __shared__ int      s_target;
    __shared__ unsigned s_prefix;
    __shared__ int      s_cnt;
    __shared__ unsigned long long s_bound;
    __shared__ float4   s_acc[MAXDET];
    __shared__ int      s_accN;
    __shared__ float4   s_gbox[GSZ];
    __shared__ unsigned s_mask[GSZ * GW];
    __shared__ unsigned s_dead[GW];

    int pair = blockIdx.x;
    int b = pair / CC;
    int t = threadIdx.x;
    const float* __restrict__ sc = g_scores_t + (size_t)pair * NPAD;
    const float4* __restrict__ bx = g_boxes + b * NN;

    if (t < MAXDET) {
        g_nms_sc[pair * MAXDET + t] = NEGV;
        g_nms_idx[pair * MAXDET + t] = 0;
    }
    if (t == 0) { s_accN = 0; s_bound = ~0ull; }

    for (int round = 0; ; round++) {
        __syncthreads();
        if (s_accN >= MAXDET) break;
        unsigned long long bound = s_bound;
        int m;

        if (round == 0) {
            // ---- fast path: fixed-cutoff compaction, no histogram ----
            if (t == 0) s_cnt = 0;
            __syncthreads();
            unsigned tau_u = __float_as_uint(TAU);
#pragma unroll 8
            for (int k = 0; k < ELEMS; k++) {
                int n = t + k * NTHR;
                float v = sc[n];
                bool f = (v > TAU);
                unsigned long long key = 0;
                if (f) {
                    unsigned u = __float_as_uint(v);
                    key = ((unsigned long long)u << 32) | (unsigned)(0xFFFFFFFFu - (unsigned)n);
                }
                int pos = warp_agg_inc(&s_cnt, f);
                if (f && pos < CAND_CAP) cand[pos] = key;
            }
            __syncthreads();
            if (s_cnt > CAND_CAP || s_cnt == 0) continue;   // exact fallback handles it
            m = s_cnt;
            if (t == 0)   // everything with score > TAU is being processed this round
                s_bound = ((unsigned long long)(tau_u + 1)) << 32;
        } else {
            // ---- exact 4-level byte-radix select among remaining ----
            if (t == 0) { s_prefix = 0u; s_total = 0; s_target = 0; }
            __syncthreads();
            unsigned prefix = 0u;
            for (int lvl = 0; lvl < 4; lvl++) {
                int shift = 24 - lvl * 8;
                if (t < 256) s_hist[t] = 0;
                __syncthreads();
                unsigned himask = (lvl == 0) ? 0u : (0xFFFFFFFFu << (shift + 8));
                for (int k = 0; k < ELEMS; k++) {
                    int n = t + k * NTHR;
                    float v = sc[n];
                    bool f = false;
                    int bin = 0;
                    if (v > 0.05f) {
                        unsigned u = __float_as_uint(v);
                        if ((u & himask) == (prefix & himask)) {
                            unsigned long long key =
                                ((unsigned long long)u << 32) | (unsigned)(0xFFFFFFFFu - (unsigned)n);
                            if (key < bound) { f = true; bin = (u >> shift) & 255; }
                        }
                    }
                    hist_add(s_hist, bin, f);
                }
                __syncthreads();
                if (t == 0) {
                    if (lvl == 0) {
                        int tot = 0;
                        for (int i = 0; i < 256; i++) tot += s_hist[i];
                        s_total = tot;
                        s_target = tot < TARGETC ? tot : TARGETC;
                    }
                    if (s_total > 0) {
                        int cum = 0, bin = 0;
                        for (int i = 255; i >= 0; i--) {
                            int h = s_hist[i];
                            if (cum + h >= s_target) { bin = i; break; }
                            cum += h;
                        }
                        s_target -= cum;
                        s_prefix |= (unsigned)bin << shift;
                    }
                }
                __syncthreads();
                prefix = s_prefix;
                if (s_total == 0) break;
            }
            if (s_total == 0) break;   // pool exhausted -> remaining slots stay NEG
            unsigned s_star = prefix;

            if (t == 0) s_cnt = 0;
            __syncthreads();
#pragma unroll 8
            for (int k = 0; k < ELEMS; k++) {
                int n = t + k * NTHR;
                float v = sc[n];
                bool f = false;
                unsigned long long key = 0;
                if (v > 0.05f) {
                    unsigned u = __float_as_uint(v);
                    if (u >= s_star) {
                        key = ((unsigned long long)u << 32) | (unsigned)(0xFFFFFFFFu - (unsigned)n);
                        if (key < bound) f = true;
                    }
                }
                int pos = warp_agg_inc(&s_cnt, f);
                if (f && pos < CAND_CAP) cand[pos] = key;
            }
            __syncthreads();
            m = s_cnt < CAND_CAP ? s_cnt : CAND_CAP;
        }

        // ---- pad + bitonic sort descending (warp-sync small substeps) ----
        int sortn = 512;
        while (sortn < m) sortn <<= 1;
        for (int i = m + t; i < sortn; i += NTHR) cand[i] = 0ull;
        __syncthreads();
        for (int k2 = 2; k2 <= sortn; k2 <<= 1) {
            for (int j = k2 >> 1; j > 0; j >>= 1) {
                for (int i = t; i < sortn; i += NTHR) {
                    int l = i ^ j;
                    if (l > i) {
                        unsigned long long a = cand[i];
                        unsigned long long bb = cand[l];
                        bool up = ((i & k2) == 0);
                        bool sw = up ? (a < bb) : (a > bb);
                        if (sw) { cand[i] = bb; cand[l] = a; }
                    }
                }
                int nj = (j > 1) ? (j >> 1) : k2;
                if (j >= 32 || nj >= 32) __syncthreads();
                else __syncwarp();
            }
        }
        if (round > 0) {
            if (t == 0) s_bound = cand[m - 1];
            __syncthreads();
        }

        // ---- walk sorted candidates in groups of GSZ ----
        for (int g0 = 0; g0 < m && s_accN < MAXDET; g0 += GSZ) {
            int gsz = min(GSZ, m - g0);
            for (int i = t; i < GSZ * GW; i += NTHR) s_mask[i] = 0u;
            if (t < GW) s_dead[t] = 0u;
            if (t < gsz) {
                unsigned long long key = cand[g0 + t];
                unsigned n = 0xFFFFFFFFu - (unsigned)(key & 0xFFFFFFFFull);
                s_gbox[t] = __ldg(&bx[n]);
            }
            __syncthreads();

            int j = t & (GSZ - 1);
            int seg = t >> 8;     // 4 work segments per candidate
            if (j < gsz) {
                float4 cb = s_gbox[j];
                bool dead = false;
                int accN = s_accN;
                for (int i = seg; i < accN; i += 4)
                    if (iou_gt_half(s_acc[i], cb)) { dead = true; break; }
                if (dead) atomicOr(&s_dead[j >> 5], 1u << (j & 31));
                for (int i = seg; i < j; i += 4)
                    if (iou_gt_half(s_gbox[i], cb))
                        atomicOr(&s_mask[i * GW + (j >> 5)], 1u << (j & 31));
            }
            __syncthreads();

            // serial in-order resolution by thread 0 (ffs over live bits)
            if (t == 0) {
                int acc = s_accN;
                int nw = (gsz + 31) >> 5;
                for (int w = 0; w < nw && acc < MAXDET; w++) {
                    unsigned valid = 0xFFFFFFFFu;
                    int rem = gsz - w * 32;
                    if (rem < 32) valid = (1u << rem) - 1u;
                    unsigned alive = ~s_dead[w] & valid;
                    while (alive && acc < MAXDET) {
                        int bit = __ffs(alive) - 1;
                        int jj = w * 32 + bit;
                        unsigned long long key = cand[g0 + jj];
                        unsigned n = 0xFFFFFFFFu - (unsigned)(key & 0xFFFFFFFFull);
                        g_nms_sc[pair * MAXDET + acc] = __uint_as_float((unsigned)(key >> 32));
                        g_nms_idx[pair * MAXDET + acc] = (int)n;
                        s_acc[acc] = s_gbox[jj];
                        acc++;
                        const unsigned* mr = &s_mask[jj * GW];
                        alive &= ~(1u << bit);
                        alive &= ~mr[w];
#pragma unroll
                        for (int w2 = 0; w2 < GW; w2++)
                            if (w2 > w) s_dead[w2] |= mr[w2];
                    }
                }
                s_accN = acc;
            }
            __syncthreads();
        }
    }
}

// ------- merge: exact 6-level u64 radix select (parallel bin scan) + tiny sort -------
__global__ __launch_bounds__(NTHR, 1) void merge_kernel(float* __restrict__ out) {
    __shared__ int      s_hist[256];
    __shared__ int      s_wsum[8];
    __shared__ unsigned long long s_prefix;
    __shared__ int      s_target;
    __shared__ int      s_newbin;
    __shared__ int      s_newtarget;
    __shared__ int      s_cnt;
    __shared__ unsigned long long ck[512];
    int b = blockIdx.x;
    int t = threadIdx.x;

    unsigned long long key[6];
    bool kv[6];
#pragma unroll
    for (int k = 0; k < 6; k++) {
        int i = t + k * NTHR;
        kv[k] = (i < FLATN);
        key[k] = 0ull;
        if (kv[k]) {
            float s = g_nms_sc[b * FLATN + i];
            unsigned u = __float_as_uint(s);
            u = (u & 0x80000000u) ? ~u : (u | 0x80000000u);
            key[k] = ((unsigned long long)u << 16) | (unsigned)(65535 - i);
        }
    }
    if (t == 0) { s_target = MAXDET; s_prefix = 0ull; }
    __syncthreads();

    unsigned long long prefix = 0ull;
    for (int lvl = 0; lvl < 6; lvl++) {
        int shift = 40 - 8 * lvl;
        if (t < 256) s_hist[t] = 0;
        __syncthreads();
        unsigned long long himask = (lvl == 0) ? 0ull : (~0ull << (shift + 8));
#pragma unroll
        for (int k = 0; k < 6; k++) {
            bool f = kv[k] && ((key[k] & himask) == prefix);
            int bin = (int)((key[k] >> shift) & 255);
            hist_add(s_hist, f ? bin : 0, f);
        }
        __syncthreads();
        // parallel suffix-sum over descending bins
        int h = 0, x = 0;
        if (t < 256) {
            int bin = 255 - t;          // t = descending rank
            h = s_hist[bin];
            x = h;
#pragma unroll
            for (int off = 1; off < 32; off <<= 1) {
                int y = __shfl_up_sync(0xffffffffu, x, off);
                if ((t & 31) >= off) x += y;
            }
            if ((t & 31) == 31) s_wsum[t >> 5] = x;
        }
        __syncthreads();
        if (t < 256) {
            int add = 0, wid = t >> 5;
            for (int w = 0; w < wid; w++) add += s_wsum[w];
            int incl = x + add, excl = incl - h;
            int target = s_target;
            if (excl < target && target <= incl) {
                s_newbin = 255 - t;
                s_newtarget = target - excl;
            }
        }
        __syncthreads();
        if (t == 0) {
            s_target = s_newtarget;
            s_prefix = prefix | ((unsigned long long)s_newbin << shift);
        }
        __syncthreads();
        prefix = s_prefix;
    }

    if (t == 0) s_cnt = 0;
    __syncthreads();
#pragma unroll
    for (int k = 0; k < 6; k++) {
        bool f = kv[k] && (key[k] >= prefix);
        int pos = warp_agg_inc(&s_cnt, f);
        if (f && pos < 512) ck[pos] = key[k];
    }
    __syncthreads();
    for (int i = s_cnt + t; i < 512; i += NTHR) ck[i] = 0ull;
    __syncthreads();

    for (int k2 = 2; k2 <= 512; k2 <<= 1) {
        for (int j = k2 >> 1; j > 0; j >>= 1) {
            if (t < 512) {
                int i = t, l = i ^ j;
                if (l > i) {
                    unsigned long long a = ck[i];
                    unsigned long long bk = ck[l];
                    bool up = ((i & k2) == 0);
                    bool sw = up ? (a < bk) : (a > bk);
                    if (sw) { ck[i] = bk; ck[l] = a; }
                }
            }
            int nj = (j > 1) ? (j >> 1) : k2;
            if (j >= 32 || nj >= 32) __syncthreads();
            else __syncwarp();
        }
    }
    __syncthreads();

    if (t < MAXDET) {
        unsigned long long kk = ck[t];
        unsigned u = (unsigned)(kk >> 16);
        float s = (u & 0x80000000u) ? __uint_as_float(u ^ 0x80000000u)
                                    : __uint_as_float(~u);
        bool valid = s > NEG_HALF;
        float b0 = -1.0f, b1 = -1.0f, b2 = -1.0f, b3 = -1.0f;
        float scv = -1.0f, lab = -1.0f;
        if (valid) {
            int flat = 65535 - (int)(kk & 0xFFFFull);
            int c = flat / MAXDET;
            int bi = g_nms_idx[b * FLATN + flat];
            float4 bb = g_boxes[b * NN + bi];
            b0 = bb.x; b1 = bb.y; b2 = bb.z; b3 = bb.w;
            scv = s;
            lab = (float)c;
        }
        out[b * (MAXDET * 4) + t * 4 + 0] = b0;
        out[b * (MAXDET * 4) + t * 4 + 1] = b1;
        out[b * (MAXDET * 4) + t * 4 + 2] = b2;
        out[b * (MAXDET * 4) + t * 4 + 3] = b3;
        out[BB * MAXDET * 4 + b * MAXDET + t] = scv;
        out[BB * MAXDET * 4 + BB * MAXDET + b * MAXDET + t] = lab;
    }
}

// ---------------- launch ----------------
extern "C" void kernel_launch(void* const* d_in, const int* in_sizes, int n_in,
                              void* d_out, int out_size) {
    const float* anchors = (const float*)d_in[1];
    const float* deltas  = (const float*)d_in[2];
    const float* cls     = (const float*)d_in[3];
    float* out = (float*)d_out;

    cudaFuncSetAttribute(nms_pair_kernel, cudaFuncAttributeMaxDynamicSharedMemorySize,
                         64 * 1024);

    prep_kernel<<<384 + BB * NTILE, 256>>>(anchors, deltas, cls);
    nms_pair_kernel<<<BB * CC, NTHR, CAND_CAP * (int)sizeof(unsigned long long)>>>();
    merge_kernel<<<BB, NTHR>>>(out);
}